// round 14
// baseline (speedup 1.0000x reference)
#include <cuda_runtime.h>
#include <math.h>

#define NB_ 16384
#define NV_ 778
#define NVP 832
#define NJ_ 16

typedef unsigned long long ull;

// ---------------- scratch (device globals; no allocation allowed) ----------
__device__ float g_pf[135 * NB_];      // pose_feature, transposed: [k][b]
__device__ float g_rel[192 * NB_];     // rel transforms (3x4 per joint), transposed: [j*12+m][b]
__device__ float g_JtJS[528];          // [j][k][11]
__device__ ull   g_vp[(NB_ / 2) * 3 * NVP + 256]; // v_posed batch-pairs [pair][c][v] (+read pad)

// ---------------- packed f32x2 helpers -------------------------------------
static __device__ __forceinline__ ull ffma2(ull a, ull b, ull c) {
    ull d;
    asm("fma.rn.f32x2 %0, %1, %2, %3;" : "=l"(d) : "l"(a), "l"(b), "l"(c));
    return d;
}
static __device__ __forceinline__ ull rep2(float x) {
    ull r;
    asm("mov.b64 %0, {%1, %1};" : "=l"(r) : "f"(x));
    return r;
}
static __device__ __forceinline__ void unpack2(ull v, float& lo, float& hi) {
    asm("mov.b64 {%0, %1}, %2;" : "=f"(lo), "=f"(hi) : "l"(v));
}

// ---------------- kernel A: batch-independent joint regressor fold ---------
__global__ void kA(const float* __restrict__ Jr, const float* __restrict__ vt,
                   const float* __restrict__ sh) {
    int wid = (blockIdx.x * blockDim.x + threadIdx.x) >> 5;
    int lane = threadIdx.x & 31;
    if (wid >= 528) return;
    int j = wid / 33, rem = wid % 33, k = rem / 11, s = rem % 11;
    float acc = 0.f;
    if (s == 0) {
        for (int v = lane; v < NV_; v += 32)
            acc = fmaf(Jr[j * NV_ + v], vt[v * 3 + k], acc);
    } else {
        int l = s - 1;
        for (int v = lane; v < NV_; v += 32)
            acc = fmaf(Jr[j * NV_ + v], sh[v * 30 + k * 10 + l], acc);
    }
#pragma unroll
    for (int o = 16; o > 0; o >>= 1) acc += __shfl_down_sync(0xffffffffu, acc, o);
    if (lane == 0) g_JtJS[(j * 3 + k) * 11 + s] = acc;
}

// ---------------- Rodrigues ------------------------------------------------
static __device__ __forceinline__ void rodrigues(float x, float y, float z, float* R) {
    float sx = x + 1e-8f, sy = y + 1e-8f, sz = z + 1e-8f;
    float angle = sqrtf(sx * sx + sy * sy + sz * sz);
    float inv = 1.f / angle;
    float ax = x * inv, ay = y * inv, az = z * inv;
    float s = sinf(angle), c = cosf(angle), C = 1.f - c;
    float xx = ax * ax, yy = ay * ay, zz = az * az;
    float xy = ax * ay, xz = ax * az, yz = ay * az;
    R[0] = 1.f - C * (yy + zz); R[1] = -s * az + C * xy;    R[2] = s * ay + C * xz;
    R[3] = s * az + C * xy;     R[4] = 1.f - C * (xx + zz); R[5] = -s * ax + C * yz;
    R[6] = -s * ay + C * xz;    R[7] = s * ax + C * yz;     R[8] = 1.f - C * (xx + yy);
}

// ---------------- kernel B: per-batch pose / chain / rel transforms --------
__global__ void kB(const float* __restrict__ betas, const float* __restrict__ go,
                   const float* __restrict__ hp, const float* __restrict__ transl,
                   const float* __restrict__ hc, const float* __restrict__ pm,
                   float* __restrict__ out_j) {
    int b = blockIdx.x * blockDim.x + threadIdx.x;
    if (b >= NB_) return;

    float h[6];
#pragma unroll
    for (int p = 0; p < 6; p++) h[p] = hp[b * 6 + p];

    float fp[48];
#pragma unroll
    for (int i = 0; i < 3; i++) fp[i] = go[b * 3 + i] + pm[i];
#pragma unroll
    for (int i = 0; i < 45; i++) {
        float a = pm[3 + i];
#pragma unroll
        for (int p = 0; p < 6; p++) a = fmaf(h[p], hc[p * 45 + i], a);
        fp[3 + i] = a;
    }

    float bt[10];
#pragma unroll
    for (int l = 0; l < 10; l++) bt[l] = betas[b * 10 + l];

    float jx[16], jy[16], jz[16];
#pragma unroll
    for (int j = 0; j < 16; j++) {
#pragma unroll
        for (int k = 0; k < 3; k++) {
            const float* e = &g_JtJS[(j * 3 + k) * 11];
            float a = e[0];
#pragma unroll
            for (int l = 0; l < 10; l++) a = fmaf(bt[l], e[1 + l], a);
            if (k == 0) jx[j] = a; else if (k == 1) jy[j] = a; else jz[j] = a;
        }
    }

    float tl0 = transl[b * 3 + 0], tl1 = transl[b * 3 + 1], tl2 = transl[b * 3 + 2];

    float W[12];
    {
        float R[9];
        rodrigues(fp[0], fp[1], fp[2], R);
        W[0] = R[0]; W[1] = R[1]; W[2] = R[2];  W[3]  = jx[0];
        W[4] = R[3]; W[5] = R[4]; W[6] = R[5];  W[7]  = jy[0];
        W[8] = R[6]; W[9] = R[7]; W[10] = R[8]; W[11] = jz[0];
        out_j[(b * 16 + 0) * 3 + 0] = W[3] + tl0;
        out_j[(b * 16 + 0) * 3 + 1] = W[7] + tl1;
        out_j[(b * 16 + 0) * 3 + 2] = W[11] + tl2;
        float tcx = W[3]  - (W[0] * jx[0] + W[1] * jy[0] + W[2] * jz[0]);
        float tcy = W[7]  - (W[4] * jx[0] + W[5] * jy[0] + W[6] * jz[0]);
        float tcz = W[11] - (W[8] * jx[0] + W[9] * jy[0] + W[10] * jz[0]);
        g_rel[(0 * 12 + 0) * NB_ + b] = W[0]; g_rel[(0 * 12 + 1) * NB_ + b] = W[1];
        g_rel[(0 * 12 + 2) * NB_ + b] = W[2]; g_rel[(0 * 12 + 3) * NB_ + b] = tcx;
        g_rel[(0 * 12 + 4) * NB_ + b] = W[4]; g_rel[(0 * 12 + 5) * NB_ + b] = W[5];
        g_rel[(0 * 12 + 6) * NB_ + b] = W[6]; g_rel[(0 * 12 + 7) * NB_ + b] = tcy;
        g_rel[(0 * 12 + 8) * NB_ + b] = W[8]; g_rel[(0 * 12 + 9) * NB_ + b] = W[9];
        g_rel[(0 * 12 + 10) * NB_ + b] = W[10]; g_rel[(0 * 12 + 11) * NB_ + b] = tcz;
    }

#pragma unroll
    for (int f = 0; f < 5; f++) {
        float cur[12];
#pragma unroll
        for (int m = 0; m < 12; m++) cur[m] = W[m];
        float pjx = jx[0], pjy = jy[0], pjz = jz[0];
#pragma unroll
        for (int s = 0; s < 3; s++) {
            int j = 3 * f + 1 + s;
            float R[9];
            rodrigues(fp[3 * j], fp[3 * j + 1], fp[3 * j + 2], R);
#pragma unroll
            for (int m = 0; m < 9; m++) {
                float pv = R[m] - ((m == 0 || m == 4 || m == 8) ? 1.f : 0.f);
                g_pf[((j - 1) * 9 + m) * NB_ + b] = pv;
            }
            float rjx = jx[j] - pjx, rjy = jy[j] - pjy, rjz = jz[j] - pjz;
            float nxt[12];
#pragma unroll
            for (int r = 0; r < 3; r++) {
                float a0 = cur[r * 4 + 0], a1 = cur[r * 4 + 1], a2 = cur[r * 4 + 2], a3 = cur[r * 4 + 3];
                nxt[r * 4 + 0] = a0 * R[0] + a1 * R[3] + a2 * R[6];
                nxt[r * 4 + 1] = a0 * R[1] + a1 * R[4] + a2 * R[7];
                nxt[r * 4 + 2] = a0 * R[2] + a1 * R[5] + a2 * R[8];
                nxt[r * 4 + 3] = a0 * rjx + a1 * rjy + a2 * rjz + a3;
            }
            out_j[(b * 16 + j) * 3 + 0] = nxt[3] + tl0;
            out_j[(b * 16 + j) * 3 + 1] = nxt[7] + tl1;
            out_j[(b * 16 + j) * 3 + 2] = nxt[11] + tl2;
            float tcx = nxt[3]  - (nxt[0] * jx[j] + nxt[1] * jy[j] + nxt[2] * jz[j]);
            float tcy = nxt[7]  - (nxt[4] * jx[j] + nxt[5] * jy[j] + nxt[6] * jz[j]);
            float tcz = nxt[11] - (nxt[8] * jx[j] + nxt[9] * jy[j] + nxt[10] * jz[j]);
            g_rel[(j * 12 + 0) * NB_ + b] = nxt[0]; g_rel[(j * 12 + 1) * NB_ + b] = nxt[1];
            g_rel[(j * 12 + 2) * NB_ + b] = nxt[2]; g_rel[(j * 12 + 3) * NB_ + b] = tcx;
            g_rel[(j * 12 + 4) * NB_ + b] = nxt[4]; g_rel[(j * 12 + 5) * NB_ + b] = nxt[5];
            g_rel[(j * 12 + 6) * NB_ + b] = nxt[6]; g_rel[(j * 12 + 7) * NB_ + b] = tcy;
            g_rel[(j * 12 + 8) * NB_ + b] = nxt[8]; g_rel[(j * 12 + 9) * NB_ + b] = nxt[9];
            g_rel[(j * 12 + 10) * NB_ + b] = nxt[10]; g_rel[(j * 12 + 11) * NB_ + b] = tcz;
#pragma unroll
            for (int m = 0; m < 12; m++) cur[m] = nxt[m];
            pjx = jx[j]; pjy = jy[j]; pjz = jz[j];
        }
    }
}

// ---------------- kernel Pose: v_posed = vt + sh@betas + pf@posedirs -------
// block = 256 = 8 warps. Warp w -> 8 batches (4 f32x2 pairs); lane -> vertex.
// k-dim in 2 chunks (68+67); smem ~50KB -> 3 CTAs/SM.
#define KCP 68

__global__ void __launch_bounds__(256, 3) kPose(
    const float* __restrict__ betas, const float* __restrict__ posedirs,
    const float* __restrict__ v_template, const float* __restrict__ shapedirs) {
    extern __shared__ float smem[];
    float* pf_s = smem;                // [KCP][64]   4352 fl
    float* pd_s = pf_s + KCP * 64;     // [KCP][96]   6528 fl
    float* sh_s = pd_s + KCP * 96;     // [32][31]    992 fl
    float* vt_s = sh_s + 32 * 31;      // [32][3]     96 fl
    float* bt_s = vt_s + 96;           // [10][64]    640 fl

    const int tid = threadIdx.x;
    const int bbase = blockIdx.x * 64;
    const int vbase = blockIdx.y * 32;

    for (int i = tid; i < 960; i += 256) {
        int vl = i / 30, r = i % 30;
        int v = vbase + vl;
        sh_s[vl * 31 + r] = (v < NV_) ? shapedirs[v * 30 + r] : 0.f;
    }
    for (int i = tid; i < 96; i += 256) {
        int g = vbase * 3 + i;
        vt_s[i] = (g < NV_ * 3) ? v_template[g] : 0.f;
    }
    for (int i = tid; i < 640; i += 256) {
        int l = i >> 6, bl = i & 63;
        bt_s[i] = betas[(bbase + bl) * 10 + l];
    }
    __syncthreads();

    const int w = tid >> 5, vl = tid & 31;
    const int bl0 = w * 8;

    ull p2[4][3];
#pragma unroll
    for (int c = 0; c < 3; c++) {
        ull t = rep2(vt_s[vl * 3 + c]);
#pragma unroll
        for (int q = 0; q < 4; q++) p2[q][c] = t;
    }
#pragma unroll
    for (int l = 0; l < 10; l++) {
        ulonglong2 bA = *reinterpret_cast<const ulonglong2*>(bt_s + l * 64 + bl0);
        ulonglong2 bB = *reinterpret_cast<const ulonglong2*>(bt_s + l * 64 + bl0 + 4);
        ull s0 = rep2(sh_s[vl * 31 + l]);
        ull s1 = rep2(sh_s[vl * 31 + 10 + l]);
        ull s2 = rep2(sh_s[vl * 31 + 20 + l]);
        p2[0][0] = ffma2(bA.x, s0, p2[0][0]); p2[0][1] = ffma2(bA.x, s1, p2[0][1]); p2[0][2] = ffma2(bA.x, s2, p2[0][2]);
        p2[1][0] = ffma2(bA.y, s0, p2[1][0]); p2[1][1] = ffma2(bA.y, s1, p2[1][1]); p2[1][2] = ffma2(bA.y, s2, p2[1][2]);
        p2[2][0] = ffma2(bB.x, s0, p2[2][0]); p2[2][1] = ffma2(bB.x, s1, p2[2][1]); p2[2][2] = ffma2(bB.x, s2, p2[2][2]);
        p2[3][0] = ffma2(bB.y, s0, p2[3][0]); p2[3][1] = ffma2(bB.y, s1, p2[3][1]); p2[3][2] = ffma2(bB.y, s2, p2[3][2]);
    }

    for (int k0 = 0; k0 < 135; k0 += KCP) {
        const int kn = (135 - k0 < KCP) ? (135 - k0) : KCP;
        __syncthreads();
        for (int i = tid; i < kn * 64; i += 256) {
            int kl = i >> 6, bl = i & 63;
            pf_s[i] = g_pf[(k0 + kl) * NB_ + bbase + bl];
        }
        for (int i = tid; i < kn * 96; i += 256) {
            int kl = i / 96, c = i % 96;
            int col = vbase * 3 + c;
            pd_s[i] = (col < NV_ * 3) ? posedirs[(size_t)(k0 + kl) * (NV_ * 3) + col] : 0.f;
        }
        __syncthreads();
#pragma unroll 4
        for (int k = 0; k < kn; k++) {
            ulonglong2 pfA = *reinterpret_cast<const ulonglong2*>(pf_s + (k << 6) + bl0);
            ulonglong2 pfB = *reinterpret_cast<const ulonglong2*>(pf_s + (k << 6) + bl0 + 4);
            const float* pd = pd_s + k * 96 + vl * 3;
            ull d0 = rep2(pd[0]);
            ull d1 = rep2(pd[1]);
            ull d2 = rep2(pd[2]);
            p2[0][0] = ffma2(pfA.x, d0, p2[0][0]); p2[0][1] = ffma2(pfA.x, d1, p2[0][1]); p2[0][2] = ffma2(pfA.x, d2, p2[0][2]);
            p2[1][0] = ffma2(pfA.y, d0, p2[1][0]); p2[1][1] = ffma2(pfA.y, d1, p2[1][1]); p2[1][2] = ffma2(pfA.y, d2, p2[1][2]);
            p2[2][0] = ffma2(pfB.x, d0, p2[2][0]); p2[2][1] = ffma2(pfB.x, d1, p2[2][1]); p2[2][2] = ffma2(pfB.x, d2, p2[2][2]);
            p2[3][0] = ffma2(pfB.y, d0, p2[3][0]); p2[3][1] = ffma2(pfB.y, d1, p2[3][1]); p2[3][2] = ffma2(pfB.y, d2, p2[3][2]);
        }
    }

    const size_t pair0 = (size_t)(bbase >> 1) + w * 4;
#pragma unroll
    for (int q = 0; q < 4; q++)
#pragma unroll
        for (int c = 0; c < 3; c++)
            g_vp[((pair0 + q) * 3 + c) * NVP + vbase + vl] = p2[q][c];
}

// ---------------- kernel LBS: out = sum_j w_j * (R_j p + t_j) + transl -----
// block = 256 = 8 warps. Warp w -> 1 batch-pair; thread -> 4 vertices
// (vl + t*32). Block tile: 16 batches x 128 vertices. Broadcast rel loads
// amortized over 4 vertices -> fma-bound. 2 CTAs/SM (register-heavy).
#define RELS 194

__global__ void __launch_bounds__(256, 2) kLBS(
    const float* __restrict__ transl, const float* __restrict__ lbsw,
    float* __restrict__ out_v) {
    extern __shared__ float smem[];
    ull*   rel_u = (ull*)smem;                  // [8 pairs][RELS]  1552 ull
    ull*   w_u   = rel_u + 8 * RELS;            // [128][17]        2176 ull
    float* tr_s  = (float*)(w_u + 128 * 17);    // [16][3]          48 fl

    const int tid = threadIdx.x;
    const int bbase = blockIdx.x * 16;
    const int vbase = blockIdx.y * 128;

    for (int i = tid; i < 192 * 8; i += 256) {
        int jm = i >> 3, pl = i & 7;
        rel_u[pl * RELS + jm] =
            *reinterpret_cast<const ull*>(g_rel + jm * NB_ + bbase + 2 * pl);
    }
    for (int i = tid; i < 128 * 16; i += 256) {
        int vl = i >> 4, j = i & 15;
        int v = vbase + vl;
        w_u[vl * 17 + j] = rep2((v < NV_) ? lbsw[v * 16 + j] : 0.f);
    }
    for (int i = tid; i < 48; i += 256) {
        tr_s[i] = transl[bbase * 3 + i];
    }
    __syncthreads();

    const int w = tid >> 5, vl = tid & 31;
    const size_t pair = (size_t)(bbase >> 1) + w;

    // load v_posed pairs for 4 vertices (coalesced LDG.64; reads past NVP
    // land in the pad and are discarded by the v < NV_ store guard)
    ull p2[4][3];
#pragma unroll
    for (int t = 0; t < 4; t++)
#pragma unroll
        for (int c = 0; c < 3; c++)
            p2[t][c] = g_vp[(pair * 3 + c) * NVP + vbase + t * 32 + vl];

    ull o2[4][3];
#pragma unroll
    for (int t = 0; t < 4; t++)
#pragma unroll
        for (int c = 0; c < 3; c++) o2[t][c] = 0ull;

#pragma unroll
    for (int j = 0; j < 16; j++) {
        const ulonglong2* Rm =
            reinterpret_cast<const ulonglong2*>(rel_u + (size_t)w * RELS + j * 12);
        ulonglong2 r01 = Rm[0], r23 = Rm[1], r45 = Rm[2];
        ulonglong2 r67 = Rm[3], r89 = Rm[4], rAB = Rm[5];
#pragma unroll
        for (int t = 0; t < 4; t++) {
            ull wv = w_u[(t * 32 + vl) * 17 + j];
            ull ux = ffma2(r01.x, p2[t][0], ffma2(r01.y, p2[t][1], ffma2(r23.x, p2[t][2], r23.y)));
            ull uy = ffma2(r45.x, p2[t][0], ffma2(r45.y, p2[t][1], ffma2(r67.x, p2[t][2], r67.y)));
            ull uz = ffma2(r89.x, p2[t][0], ffma2(r89.y, p2[t][1], ffma2(rAB.x, p2[t][2], rAB.y)));
            o2[t][0] = ffma2(wv, ux, o2[t][0]);
            o2[t][1] = ffma2(wv, uy, o2[t][1]);
            o2[t][2] = ffma2(wv, uz, o2[t][2]);
        }
    }

    const int b0 = bbase + 2 * w;
#pragma unroll
    for (int t = 0; t < 4; t++) {
        const int v = vbase + t * 32 + vl;
        if (v < NV_) {
#pragma unroll
            for (int c = 0; c < 3; c++) {
                float lo, hi;
                unpack2(o2[t][c], lo, hi);
                out_v[((size_t)b0 * NV_ + v) * 3 + c]       = lo + tr_s[(2 * w) * 3 + c];
                out_v[((size_t)(b0 + 1) * NV_ + v) * 3 + c] = hi + tr_s[(2 * w + 1) * 3 + c];
            }
        }
    }
}

// ---------------- launch ---------------------------------------------------
extern "C" void kernel_launch(void* const* d_in, const int* in_sizes, int n_in,
                              void* d_out, int out_size) {
    const float* betas   = (const float*)d_in[0];
    const float* go      = (const float*)d_in[1];
    const float* hp      = (const float*)d_in[2];
    const float* transl  = (const float*)d_in[3];
    const float* hc      = (const float*)d_in[4];
    const float* pm      = (const float*)d_in[5];
    const float* vt      = (const float*)d_in[6];
    const float* sh      = (const float*)d_in[7];
    const float* pd      = (const float*)d_in[8];
    const float* Jr      = (const float*)d_in[9];
    const float* lw      = (const float*)d_in[10];
    float* out = (float*)d_out;
    float* out_j = out + (size_t)NB_ * NV_ * 3;

    kA<<<66, 256>>>(Jr, vt, sh);
    kB<<<NB_ / 256, 256>>>(betas, go, hp, transl, hc, pm, out_j);

    const int smem_pose = (KCP * 64 + KCP * 96 + 32 * 31 + 96 + 640) * 4;
    cudaFuncSetAttribute(kPose, cudaFuncAttributeMaxDynamicSharedMemorySize, smem_pose);
    dim3 gp(NB_ / 64, NVP / 32);
    kPose<<<gp, 256, smem_pose>>>(betas, pd, vt, sh);

    const int smem_lbs = (8 * RELS + 128 * 17) * 8 + 48 * 4;
    cudaFuncSetAttribute(kLBS, cudaFuncAttributeMaxDynamicSharedMemorySize, smem_lbs);
    dim3 gl(NB_ / 16, (NVP + 127) / 128);
    kLBS<<<gl, 256, smem_lbs>>>(transl, lw, out);
}

// round 15
// speedup vs baseline: 1.4390x; 1.4390x over previous
#include <cuda_runtime.h>
#include <math.h>

#define NB_ 16384
#define NV_ 778
#define NVP 832
#define NJ_ 16

typedef unsigned long long ull;

// ---------------- scratch (device globals; no allocation allowed) ----------
__device__ float g_pf[135 * NB_];      // pose_feature, transposed: [k][b]
__device__ float g_rel[192 * NB_];     // rel transforms (3x4 per joint), transposed: [j*12+m][b]
__device__ float g_JtJS[528];          // [j][k][11]
__device__ ull   g_vp[(NB_ / 2) * 3 * NVP + 256]; // v_posed batch-pairs [pair][c][v]

// ---------------- packed f32x2 helpers -------------------------------------
static __device__ __forceinline__ ull ffma2(ull a, ull b, ull c) {
    ull d;
    asm("fma.rn.f32x2 %0, %1, %2, %3;" : "=l"(d) : "l"(a), "l"(b), "l"(c));
    return d;
}
static __device__ __forceinline__ ull rep2(float x) {
    ull r;
    asm("mov.b64 %0, {%1, %1};" : "=l"(r) : "f"(x));
    return r;
}
static __device__ __forceinline__ void unpack2(ull v, float& lo, float& hi) {
    asm("mov.b64 {%0, %1}, %2;" : "=f"(lo), "=f"(hi) : "l"(v));
}

// ---------------- kernel A: batch-independent joint regressor fold ---------
__global__ void kA(const float* __restrict__ Jr, const float* __restrict__ vt,
                   const float* __restrict__ sh) {
    int wid = (blockIdx.x * blockDim.x + threadIdx.x) >> 5;
    int lane = threadIdx.x & 31;
    if (wid >= 528) return;
    int j = wid / 33, rem = wid % 33, k = rem / 11, s = rem % 11;
    float acc = 0.f;
    if (s == 0) {
        for (int v = lane; v < NV_; v += 32)
            acc = fmaf(Jr[j * NV_ + v], vt[v * 3 + k], acc);
    } else {
        int l = s - 1;
        for (int v = lane; v < NV_; v += 32)
            acc = fmaf(Jr[j * NV_ + v], sh[v * 30 + k * 10 + l], acc);
    }
#pragma unroll
    for (int o = 16; o > 0; o >>= 1) acc += __shfl_down_sync(0xffffffffu, acc, o);
    if (lane == 0) g_JtJS[(j * 3 + k) * 11 + s] = acc;
}

// ---------------- Rodrigues ------------------------------------------------
static __device__ __forceinline__ void rodrigues(float x, float y, float z, float* R) {
    float sx = x + 1e-8f, sy = y + 1e-8f, sz = z + 1e-8f;
    float angle = sqrtf(sx * sx + sy * sy + sz * sz);
    float inv = 1.f / angle;
    float ax = x * inv, ay = y * inv, az = z * inv;
    float s = sinf(angle), c = cosf(angle), C = 1.f - c;
    float xx = ax * ax, yy = ay * ay, zz = az * az;
    float xy = ax * ay, xz = ax * az, yz = ay * az;
    R[0] = 1.f - C * (yy + zz); R[1] = -s * az + C * xy;    R[2] = s * ay + C * xz;
    R[3] = s * az + C * xy;     R[4] = 1.f - C * (xx + zz); R[5] = -s * ax + C * yz;
    R[6] = -s * ay + C * xz;    R[7] = s * ax + C * yz;     R[8] = 1.f - C * (xx + yy);
}

// ---------------- kernel B: per-batch pose / chain / rel transforms --------
__global__ void kB(const float* __restrict__ betas, const float* __restrict__ go,
                   const float* __restrict__ hp, const float* __restrict__ transl,
                   const float* __restrict__ hc, const float* __restrict__ pm,
                   float* __restrict__ out_j) {
    int b = blockIdx.x * blockDim.x + threadIdx.x;
    if (b >= NB_) return;

    float h[6];
#pragma unroll
    for (int p = 0; p < 6; p++) h[p] = hp[b * 6 + p];

    float fp[48];
#pragma unroll
    for (int i = 0; i < 3; i++) fp[i] = go[b * 3 + i] + pm[i];
#pragma unroll
    for (int i = 0; i < 45; i++) {
        float a = pm[3 + i];
#pragma unroll
        for (int p = 0; p < 6; p++) a = fmaf(h[p], hc[p * 45 + i], a);
        fp[3 + i] = a;
    }

    float bt[10];
#pragma unroll
    for (int l = 0; l < 10; l++) bt[l] = betas[b * 10 + l];

    float jx[16], jy[16], jz[16];
#pragma unroll
    for (int j = 0; j < 16; j++) {
#pragma unroll
        for (int k = 0; k < 3; k++) {
            const float* e = &g_JtJS[(j * 3 + k) * 11];
            float a = e[0];
#pragma unroll
            for (int l = 0; l < 10; l++) a = fmaf(bt[l], e[1 + l], a);
            if (k == 0) jx[j] = a; else if (k == 1) jy[j] = a; else jz[j] = a;
        }
    }

    float tl0 = transl[b * 3 + 0], tl1 = transl[b * 3 + 1], tl2 = transl[b * 3 + 2];

    float W[12];
    {
        float R[9];
        rodrigues(fp[0], fp[1], fp[2], R);
        W[0] = R[0]; W[1] = R[1]; W[2] = R[2];  W[3]  = jx[0];
        W[4] = R[3]; W[5] = R[4]; W[6] = R[5];  W[7]  = jy[0];
        W[8] = R[6]; W[9] = R[7]; W[10] = R[8]; W[11] = jz[0];
        out_j[(b * 16 + 0) * 3 + 0] = W[3] + tl0;
        out_j[(b * 16 + 0) * 3 + 1] = W[7] + tl1;
        out_j[(b * 16 + 0) * 3 + 2] = W[11] + tl2;
        float tcx = W[3]  - (W[0] * jx[0] + W[1] * jy[0] + W[2] * jz[0]);
        float tcy = W[7]  - (W[4] * jx[0] + W[5] * jy[0] + W[6] * jz[0]);
        float tcz = W[11] - (W[8] * jx[0] + W[9] * jy[0] + W[10] * jz[0]);
        g_rel[(0 * 12 + 0) * NB_ + b] = W[0]; g_rel[(0 * 12 + 1) * NB_ + b] = W[1];
        g_rel[(0 * 12 + 2) * NB_ + b] = W[2]; g_rel[(0 * 12 + 3) * NB_ + b] = tcx;
        g_rel[(0 * 12 + 4) * NB_ + b] = W[4]; g_rel[(0 * 12 + 5) * NB_ + b] = W[5];
        g_rel[(0 * 12 + 6) * NB_ + b] = W[6]; g_rel[(0 * 12 + 7) * NB_ + b] = tcy;
        g_rel[(0 * 12 + 8) * NB_ + b] = W[8]; g_rel[(0 * 12 + 9) * NB_ + b] = W[9];
        g_rel[(0 * 12 + 10) * NB_ + b] = W[10]; g_rel[(0 * 12 + 11) * NB_ + b] = tcz;
    }

#pragma unroll
    for (int f = 0; f < 5; f++) {
        float cur[12];
#pragma unroll
        for (int m = 0; m < 12; m++) cur[m] = W[m];
        float pjx = jx[0], pjy = jy[0], pjz = jz[0];
#pragma unroll
        for (int s = 0; s < 3; s++) {
            int j = 3 * f + 1 + s;
            float R[9];
            rodrigues(fp[3 * j], fp[3 * j + 1], fp[3 * j + 2], R);
#pragma unroll
            for (int m = 0; m < 9; m++) {
                float pv = R[m] - ((m == 0 || m == 4 || m == 8) ? 1.f : 0.f);
                g_pf[((j - 1) * 9 + m) * NB_ + b] = pv;
            }
            float rjx = jx[j] - pjx, rjy = jy[j] - pjy, rjz = jz[j] - pjz;
            float nxt[12];
#pragma unroll
            for (int r = 0; r < 3; r++) {
                float a0 = cur[r * 4 + 0], a1 = cur[r * 4 + 1], a2 = cur[r * 4 + 2], a3 = cur[r * 4 + 3];
                nxt[r * 4 + 0] = a0 * R[0] + a1 * R[3] + a2 * R[6];
                nxt[r * 4 + 1] = a0 * R[1] + a1 * R[4] + a2 * R[7];
                nxt[r * 4 + 2] = a0 * R[2] + a1 * R[5] + a2 * R[8];
                nxt[r * 4 + 3] = a0 * rjx + a1 * rjy + a2 * rjz + a3;
            }
            out_j[(b * 16 + j) * 3 + 0] = nxt[3] + tl0;
            out_j[(b * 16 + j) * 3 + 1] = nxt[7] + tl1;
            out_j[(b * 16 + j) * 3 + 2] = nxt[11] + tl2;
            float tcx = nxt[3]  - (nxt[0] * jx[j] + nxt[1] * jy[j] + nxt[2] * jz[j]);
            float tcy = nxt[7]  - (nxt[4] * jx[j] + nxt[5] * jy[j] + nxt[6] * jz[j]);
            float tcz = nxt[11] - (nxt[8] * jx[j] + nxt[9] * jy[j] + nxt[10] * jz[j]);
            g_rel[(j * 12 + 0) * NB_ + b] = nxt[0]; g_rel[(j * 12 + 1) * NB_ + b] = nxt[1];
            g_rel[(j * 12 + 2) * NB_ + b] = nxt[2]; g_rel[(j * 12 + 3) * NB_ + b] = tcx;
            g_rel[(j * 12 + 4) * NB_ + b] = nxt[4]; g_rel[(j * 12 + 5) * NB_ + b] = nxt[5];
            g_rel[(j * 12 + 6) * NB_ + b] = nxt[6]; g_rel[(j * 12 + 7) * NB_ + b] = tcy;
            g_rel[(j * 12 + 8) * NB_ + b] = nxt[8]; g_rel[(j * 12 + 9) * NB_ + b] = nxt[9];
            g_rel[(j * 12 + 10) * NB_ + b] = nxt[10]; g_rel[(j * 12 + 11) * NB_ + b] = tcz;
#pragma unroll
            for (int m = 0; m < 12; m++) cur[m] = nxt[m];
            pjx = jx[j]; pjy = jy[j]; pjz = jz[j];
        }
    }
}

// ---------------- kernel Pose: v_posed = vt + sh@betas + pf@posedirs -------
// block = 256 = 8 warps. Warp w -> 8 batches (4 f32x2 pairs); lane -> vertex.
// k-dim in 3 chunks of 45; smem ~35.7KB -> 4 CTAs/SM (reg cap 64).
#define KCP 45

__global__ void __launch_bounds__(256, 4) kPose(
    const float* __restrict__ betas, const float* __restrict__ posedirs,
    const float* __restrict__ v_template, const float* __restrict__ shapedirs) {
    extern __shared__ float smem[];
    float* pf_s = smem;                // [KCP][64]   2880 fl
    float* pd_s = pf_s + KCP * 64;     // [KCP][96]   4320 fl
    float* sh_s = pd_s + KCP * 96;     // [32][31]    992 fl
    float* vt_s = sh_s + 32 * 31;      // [32][3]     96 fl
    float* bt_s = vt_s + 96;           // [10][64]    640 fl

    const int tid = threadIdx.x;
    const int bbase = blockIdx.x * 64;
    const int vbase = blockIdx.y * 32;

    for (int i = tid; i < 960; i += 256) {
        int vl = i / 30, r = i % 30;
        int v = vbase + vl;
        sh_s[vl * 31 + r] = (v < NV_) ? shapedirs[v * 30 + r] : 0.f;
    }
    for (int i = tid; i < 96; i += 256) {
        int g = vbase * 3 + i;
        vt_s[i] = (g < NV_ * 3) ? v_template[g] : 0.f;
    }
    for (int i = tid; i < 640; i += 256) {
        int l = i >> 6, bl = i & 63;
        bt_s[i] = betas[(bbase + bl) * 10 + l];
    }
    __syncthreads();

    const int w = tid >> 5, vl = tid & 31;
    const int bl0 = w * 8;

    ull p2[4][3];
#pragma unroll
    for (int c = 0; c < 3; c++) {
        ull t = rep2(vt_s[vl * 3 + c]);
#pragma unroll
        for (int q = 0; q < 4; q++) p2[q][c] = t;
    }
#pragma unroll
    for (int l = 0; l < 10; l++) {
        ulonglong2 bA = *reinterpret_cast<const ulonglong2*>(bt_s + l * 64 + bl0);
        ulonglong2 bB = *reinterpret_cast<const ulonglong2*>(bt_s + l * 64 + bl0 + 4);
        ull s0 = rep2(sh_s[vl * 31 + l]);
        ull s1 = rep2(sh_s[vl * 31 + 10 + l]);
        ull s2 = rep2(sh_s[vl * 31 + 20 + l]);
        p2[0][0] = ffma2(bA.x, s0, p2[0][0]); p2[0][1] = ffma2(bA.x, s1, p2[0][1]); p2[0][2] = ffma2(bA.x, s2, p2[0][2]);
        p2[1][0] = ffma2(bA.y, s0, p2[1][0]); p2[1][1] = ffma2(bA.y, s1, p2[1][1]); p2[1][2] = ffma2(bA.y, s2, p2[1][2]);
        p2[2][0] = ffma2(bB.x, s0, p2[2][0]); p2[2][1] = ffma2(bB.x, s1, p2[2][1]); p2[2][2] = ffma2(bB.x, s2, p2[2][2]);
        p2[3][0] = ffma2(bB.y, s0, p2[3][0]); p2[3][1] = ffma2(bB.y, s1, p2[3][1]); p2[3][2] = ffma2(bB.y, s2, p2[3][2]);
    }

    for (int k0 = 0; k0 < 135; k0 += KCP) {
        __syncthreads();
        for (int i = tid; i < KCP * 64; i += 256) {
            int kl = i >> 6, bl = i & 63;
            pf_s[i] = g_pf[(k0 + kl) * NB_ + bbase + bl];
        }
        for (int i = tid; i < KCP * 96; i += 256) {
            int kl = i / 96, c = i % 96;
            int col = vbase * 3 + c;
            pd_s[i] = (col < NV_ * 3) ? posedirs[(size_t)(k0 + kl) * (NV_ * 3) + col] : 0.f;
        }
        __syncthreads();
#pragma unroll 3
        for (int k = 0; k < KCP; k++) {
            ulonglong2 pfA = *reinterpret_cast<const ulonglong2*>(pf_s + (k << 6) + bl0);
            ulonglong2 pfB = *reinterpret_cast<const ulonglong2*>(pf_s + (k << 6) + bl0 + 4);
            const float* pd = pd_s + k * 96 + vl * 3;
            ull d0 = rep2(pd[0]);
            ull d1 = rep2(pd[1]);
            ull d2 = rep2(pd[2]);
            p2[0][0] = ffma2(pfA.x, d0, p2[0][0]); p2[0][1] = ffma2(pfA.x, d1, p2[0][1]); p2[0][2] = ffma2(pfA.x, d2, p2[0][2]);
            p2[1][0] = ffma2(pfA.y, d0, p2[1][0]); p2[1][1] = ffma2(pfA.y, d1, p2[1][1]); p2[1][2] = ffma2(pfA.y, d2, p2[1][2]);
            p2[2][0] = ffma2(pfB.x, d0, p2[2][0]); p2[2][1] = ffma2(pfB.x, d1, p2[2][1]); p2[2][2] = ffma2(pfB.x, d2, p2[2][2]);
            p2[3][0] = ffma2(pfB.y, d0, p2[3][0]); p2[3][1] = ffma2(pfB.y, d1, p2[3][1]); p2[3][2] = ffma2(pfB.y, d2, p2[3][2]);
        }
    }

    const size_t pair0 = (size_t)(bbase >> 1) + w * 4;
#pragma unroll
    for (int q = 0; q < 4; q++)
#pragma unroll
        for (int c = 0; c < 3; c++)
            g_vp[((pair0 + q) * 3 + c) * NVP + vbase + vl] = p2[q][c];
}

// ---------------- kernel LBS: out = sum_j w_j * (R_j p + t_j) + transl -----
// block = 256 = 8 warps. Warp w -> 1 batch-pair; thread -> 2 vertices
// (vl, vl+32). Block tile: 16 batches x 64 vertices. smem ~21KB -> 4 CTAs/SM.
#define RELS 194

__global__ void __launch_bounds__(256, 4) kLBS(
    const float* __restrict__ transl, const float* __restrict__ lbsw,
    float* __restrict__ out_v) {
    extern __shared__ float smem[];
    ull*   rel_u = (ull*)smem;                  // [8 pairs][RELS]  1552 ull
    ull*   w_u   = rel_u + 8 * RELS;            // [64][17]         1088 ull
    float* tr_s  = (float*)(w_u + 64 * 17);     // [16][3]          48 fl

    const int tid = threadIdx.x;
    const int bbase = blockIdx.x * 16;
    const int vbase = blockIdx.y * 64;

    for (int i = tid; i < 192 * 8; i += 256) {
        int jm = i >> 3, pl = i & 7;
        rel_u[pl * RELS + jm] =
            *reinterpret_cast<const ull*>(g_rel + jm * NB_ + bbase + 2 * pl);
    }
    for (int i = tid; i < 64 * 16; i += 256) {
        int vl = i >> 4, j = i & 15;
        int v = vbase + vl;
        w_u[vl * 17 + j] = rep2((v < NV_) ? lbsw[v * 16 + j] : 0.f);
    }
    for (int i = tid; i < 48; i += 256) {
        tr_s[i] = transl[bbase * 3 + i];
    }
    __syncthreads();

    const int w = tid >> 5, vl = tid & 31;
    const size_t pair = (size_t)(bbase >> 1) + w;

    ull p2[2][3];
#pragma unroll
    for (int t = 0; t < 2; t++)
#pragma unroll
        for (int c = 0; c < 3; c++)
            p2[t][c] = g_vp[(pair * 3 + c) * NVP + vbase + t * 32 + vl];

    ull o2[2][3];
#pragma unroll
    for (int t = 0; t < 2; t++)
#pragma unroll
        for (int c = 0; c < 3; c++) o2[t][c] = 0ull;

#pragma unroll
    for (int j = 0; j < 16; j++) {
        const ulonglong2* Rm =
            reinterpret_cast<const ulonglong2*>(rel_u + (size_t)w * RELS + j * 12);
        ulonglong2 r01 = Rm[0], r23 = Rm[1], r45 = Rm[2];
        ulonglong2 r67 = Rm[3], r89 = Rm[4], rAB = Rm[5];
        ull wv0 = w_u[vl * 17 + j];
        ull wv1 = w_u[(vl + 32) * 17 + j];
#pragma unroll
        for (int t = 0; t < 2; t++) {
            ull wv = t ? wv1 : wv0;
            ull ux = ffma2(r01.x, p2[t][0], ffma2(r01.y, p2[t][1], ffma2(r23.x, p2[t][2], r23.y)));
            ull uy = ffma2(r45.x, p2[t][0], ffma2(r45.y, p2[t][1], ffma2(r67.x, p2[t][2], r67.y)));
            ull uz = ffma2(r89.x, p2[t][0], ffma2(r89.y, p2[t][1], ffma2(rAB.x, p2[t][2], rAB.y)));
            o2[t][0] = ffma2(wv, ux, o2[t][0]);
            o2[t][1] = ffma2(wv, uy, o2[t][1]);
            o2[t][2] = ffma2(wv, uz, o2[t][2]);
        }
    }

    const int b0 = bbase + 2 * w;
#pragma unroll
    for (int t = 0; t < 2; t++) {
        const int v = vbase + t * 32 + vl;
        if (v < NV_) {
#pragma unroll
            for (int c = 0; c < 3; c++) {
                float lo, hi;
                unpack2(o2[t][c], lo, hi);
                out_v[((size_t)b0 * NV_ + v) * 3 + c]       = lo + tr_s[(2 * w) * 3 + c];
                out_v[((size_t)(b0 + 1) * NV_ + v) * 3 + c] = hi + tr_s[(2 * w + 1) * 3 + c];
            }
        }
    }
}

// ---------------- launch ---------------------------------------------------
extern "C" void kernel_launch(void* const* d_in, const int* in_sizes, int n_in,
                              void* d_out, int out_size) {
    const float* betas   = (const float*)d_in[0];
    const float* go      = (const float*)d_in[1];
    const float* hp      = (const float*)d_in[2];
    const float* transl  = (const float*)d_in[3];
    const float* hc      = (const float*)d_in[4];
    const float* pm      = (const float*)d_in[5];
    const float* vt      = (const float*)d_in[6];
    const float* sh      = (const float*)d_in[7];
    const float* pd      = (const float*)d_in[8];
    const float* Jr      = (const float*)d_in[9];
    const float* lw      = (const float*)d_in[10];
    float* out = (float*)d_out;
    float* out_j = out + (size_t)NB_ * NV_ * 3;

    kA<<<66, 256>>>(Jr, vt, sh);
    kB<<<NB_ / 256, 256>>>(betas, go, hp, transl, hc, pm, out_j);

    const int smem_pose = (KCP * 64 + KCP * 96 + 32 * 31 + 96 + 640) * 4;
    cudaFuncSetAttribute(kPose, cudaFuncAttributeMaxDynamicSharedMemorySize, smem_pose);
    dim3 gp(NB_ / 64, NVP / 32);
    kPose<<<gp, 256, smem_pose>>>(betas, pd, vt, sh);

    const int smem_lbs = (8 * RELS + 64 * 17) * 8 + 48 * 4;
    cudaFuncSetAttribute(kLBS, cudaFuncAttributeMaxDynamicSharedMemorySize, smem_lbs);
    dim3 gl(NB_ / 16, NVP / 64);
    kLBS<<<gl, 256, smem_lbs>>>(transl, lw, out);
}